// round 10
// baseline (speedup 1.0000x reference)
#include <cuda_runtime.h>
#include <cuda_fp16.h>
#include <stdint.h>

#define NU 100000
#define NB 50000
#define NN 150000
#define D  64
#define NE 2400000

#define SCAN_BLK 1024
#define NBLK ((NN + SCAN_BLK - 1) / SCAN_BLK)   // 147
#define NBINS 256
#define NPAIR (NN / 2)                           // 75000

// ---------------- scratch (device globals: allocation-free) ----------------
__device__ __half g_h16A[NN * D];    // fp16 prescaled: p0, then p2
__device__ __half g_h16B[NN * D];    // fp16 prescaled: p1
__device__ int    g_deg[NN];
__device__ float  g_dinv[NN];        // deg^-1/2
__device__ float  g_dinv2[NN];       // deg^-1
__device__ float  g_sdeg[NN];        // deg^1/2 (0 if deg=0)
__device__ int    g_off[NN + 1];
__device__ int    g_cur[NN];
__device__ int    g_csr[NE];         // frm only
__device__ int    g_partial[NBLK];
__device__ int    g_bins[NBINS];
__device__ int    g_bin_ctr[NBINS];
__device__ int    g_perm[NN];        // nodes sorted by degree (descending)

// ---------------- kernels ----------------

__global__ void k_emb0(const float* __restrict__ emb,
                       const float* __restrict__ uf,
                       const float* __restrict__ bnf,
                       const float* __restrict__ bgf,
                       const float* __restrict__ Wu, const float* __restrict__ bu,
                       const float* __restrict__ Wn, const float* __restrict__ bn,
                       const float* __restrict__ Wg, const float* __restrict__ bg,
                       float* __restrict__ out_emb0) {
    int node = blockIdx.x * 4 + (threadIdx.x >> 6);
    int d    = threadIdx.x & 63;
    if (node >= NN) return;
    float v = emb[node * D + d];
    if (node < NU) {
        const float* f = uf + node * 16;
        float s = bu[d];
#pragma unroll
        for (int k = 0; k < 16; k++) s += f[k] * Wu[k * D + d];
        v += s;
    } else {
        int b = node - NU;
        float s = bn[d] + bg[d];
        const float* fn = bnf + b * 8;
#pragma unroll
        for (int k = 0; k < 8; k++) s += fn[k] * Wn[k * D + d];
        const float* fg = bgf + b * 32;
#pragma unroll
        for (int k = 0; k < 32; k++) s += fg[k] * Wg[k * D + d];
        v += s;
    }
    out_emb0[node * D + d] = v;
}

__global__ void k_prescale0(const float* __restrict__ out_emb0) {
    int node = blockIdx.x * 4 + (threadIdx.x >> 6);
    int d    = threadIdx.x & 63;
    if (node >= NN) return;
    float di = g_dinv[node];
    int o = node * D + d;
    g_h16A[o] = __float2half_rn(di * out_emb0[o]);
}

__global__ void k_degree(const int* __restrict__ to) {
    int e = blockIdx.x * blockDim.x + threadIdx.x;
    if (e < NE) atomicAdd(&g_deg[to[e]], 1);
}

__global__ void k_scan1() {
    __shared__ int s[SCAN_BLK / 32];
    __shared__ int hist[NBINS];
    int t = threadIdx.x;
    for (int b = t; b < NBINS; b += SCAN_BLK) hist[b] = 0;
    __syncthreads();
    int i = blockIdx.x * SCAN_BLK + t;
    int v = (i < NN) ? g_deg[i] : 0;
    if (i < NN) {
        float fv = (float)v;
        float di = (v > 0) ? rsqrtf(fv) : 0.0f;
        g_dinv[i]  = di;
        g_dinv2[i] = di * di;
        g_sdeg[i]  = (v > 0) ? sqrtf(fv) : 0.0f;
        atomicAdd(&hist[min(v, NBINS - 1)], 1);
    }
    int w = v;
#pragma unroll
    for (int o = 16; o > 0; o >>= 1) w += __shfl_down_sync(0xffffffffu, w, o);
    if ((t & 31) == 0) s[t >> 5] = w;
    __syncthreads();
    if (t < SCAN_BLK / 32) {
        int x = s[t];
#pragma unroll
        for (int o = 16; o > 0; o >>= 1) x += __shfl_down_sync(0xffffffffu, x, o);
        if (t == 0) g_partial[blockIdx.x] = x;
    }
    __syncthreads();
    for (int b = t; b < NBINS; b += SCAN_BLK)
        if (hist[b]) atomicAdd(&g_bins[b], hist[b]);
}

__global__ void k_scan3_place() {
    __shared__ int s[SCAN_BLK];
    __shared__ int sp[256];
    __shared__ int sb[256];
    int t = threadIdx.x;

    if (t < 256) {
        sp[t] = (t < NBLK) ? g_partial[t] : 0;
        sb[t] = g_bins[t];
    }
    __syncthreads();
#pragma unroll
    for (int o = 1; o < 256; o <<= 1) {
        int yp = 0, yb = 0;
        if (t < 256 && t >= o) { yp = sp[t - o]; yb = sb[t - o]; }
        __syncthreads();
        if (t < 256) { sp[t] += yp; sb[t] += yb; }
        __syncthreads();
    }
    int blockBase = (blockIdx.x > 0) ? sp[blockIdx.x - 1] : 0;

    int i = blockIdx.x * SCAN_BLK + t;
    int v = (i < NN) ? g_deg[i] : 0;
    s[t] = v;
    __syncthreads();
#pragma unroll
    for (int o = 1; o < SCAN_BLK; o <<= 1) {
        int y = (t >= o) ? s[t - o] : 0;
        __syncthreads();
        s[t] += y;
        __syncthreads();
    }
    if (i < NN) {
        int ex = blockBase + s[t] - v;
        g_off[i] = ex;
        g_cur[i] = ex;
        int b = min(v, NBINS - 1);
        int binBase = (b > 0) ? sb[b - 1] : 0;
        int p = binBase + atomicAdd(&g_bin_ctr[b], 1);
        g_perm[NN - 1 - p] = i;   // descending degree
    }
    if (i == NN - 1) g_off[NN] = NE;
}

__global__ void k_scatter(const int* __restrict__ frm, const int* __restrict__ to) {
    int e = blockIdx.x * blockDim.x + threadIdx.x;
    if (e < NE) {
        int p = atomicAdd(&g_cur[to[e]], 1);
        g_csr[p] = frm[e];
    }
}

// ---- 2-node interleaved gather: doubles load MLP per 8-lane group ----
#define ACCUM(A0, A1, X)                                            \
    do {                                                            \
        float2 _f0 = __half22float2(*(const __half2*)&(X).x);       \
        float2 _f1 = __half22float2(*(const __half2*)&(X).y);       \
        float2 _f2 = __half22float2(*(const __half2*)&(X).z);       \
        float2 _f3 = __half22float2(*(const __half2*)&(X).w);       \
        (A0).x += _f0.x; (A0).y += _f0.y;                           \
        (A0).z += _f1.x; (A0).w += _f1.y;                           \
        (A1).x += _f2.x; (A1).y += _f2.y;                           \
        (A1).z += _f3.x; (A1).w += _f3.y;                           \
    } while (0)

__device__ __forceinline__ void gather2(const uint4* __restrict__ src16,
                                        int n0, int n1, int lane,
                                        float4& A0, float4& A1,
                                        float4& B0, float4& B1) {
    int i0 = g_off[n0], e0 = g_off[n0 + 1];
    int i1 = g_off[n1], e1 = g_off[n1 + 1];
    // common part: two independent load chains in flight
    int m = min(e0 - i0, e1 - i1);
#pragma unroll 2
    for (int j = 0; j < m; j++) {
        int f0 = __ldg(&g_csr[i0 + j]);
        int f1 = __ldg(&g_csr[i1 + j]);
        uint4 x0 = src16[f0 * 8 + lane];
        uint4 x1 = src16[f1 * 8 + lane];
        ACCUM(A0, A1, x0);
        ACCUM(B0, B1, x1);
    }
    i0 += m; i1 += m;
    // tails (short: nodes paired by similar degree)
#pragma unroll 2
    for (; i0 < e0; i0++) {
        int f0 = __ldg(&g_csr[i0]);
        uint4 x0 = src16[f0 * 8 + lane];
        ACCUM(A0, A1, x0);
    }
#pragma unroll 2
    for (; i1 < e1; i1++) {
        int f1 = __ldg(&g_csr[i1]);
        uint4 x1 = src16[f1 * 8 + lane];
        ACCUM(B0, B1, x1);
    }
}

__device__ __forceinline__ void store_mid(__half* __restrict__ dst, int node, int lane,
                                          const float4& a0, const float4& a1) {
    float d2 = g_dinv2[node];
    __half2 h0 = __floats2half2_rn(d2 * a0.x, d2 * a0.y);
    __half2 h1 = __floats2half2_rn(d2 * a0.z, d2 * a0.w);
    __half2 h2 = __floats2half2_rn(d2 * a1.x, d2 * a1.y);
    __half2 h3 = __floats2half2_rn(d2 * a1.z, d2 * a1.w);
    uint4 hx;
    hx.x = *(const unsigned*)&h0;
    hx.y = *(const unsigned*)&h1;
    hx.z = *(const unsigned*)&h2;
    hx.w = *(const unsigned*)&h3;
    ((uint4*)dst)[node * 8 + lane] = hx;
}

// mid layer: pairs of degree-adjacent nodes
__global__ void __launch_bounds__(256) k_prop_mid(const __half* __restrict__ src,
                                                  __half* __restrict__ dst) {
    int pair = (blockIdx.x * blockDim.x + threadIdx.x) >> 3;
    int lane = threadIdx.x & 7;
    if (pair >= NPAIR) return;
    int n0 = g_perm[2 * pair];
    int n1 = g_perm[2 * pair + 1];
    float4 A0 = make_float4(0.f, 0.f, 0.f, 0.f), A1 = A0, B0 = A0, B1 = A0;
    gather2((const uint4*)src, n0, n1, lane, A0, A1, B0, B1);
    store_mid(dst, n0, lane, A0, A1);
    store_mid(dst, n1, lane, B0, B1);
}

__device__ __forceinline__ void store_final(const __half* __restrict__ p2src,
                                            const __half* __restrict__ p1src,
                                            const float4* __restrict__ emb0_4,
                                            float4* __restrict__ acc4,
                                            int node, int lane,
                                            const float4& a0, const float4& a1) {
    float di = g_dinv[node];
    float sd = g_sdeg[node];
    int ho = node * 8 + lane;
    uint4 x1 = ((const uint4*)p1src)[ho];
    uint4 x2 = ((const uint4*)p2src)[ho];
    float2 p0 = __half22float2(*(const __half2*)&x1.x);
    float2 p1 = __half22float2(*(const __half2*)&x1.y);
    float2 p2 = __half22float2(*(const __half2*)&x1.z);
    float2 p3 = __half22float2(*(const __half2*)&x1.w);
    float2 q0 = __half22float2(*(const __half2*)&x2.x);
    float2 q1 = __half22float2(*(const __half2*)&x2.y);
    float2 q2 = __half22float2(*(const __half2*)&x2.z);
    float2 q3 = __half22float2(*(const __half2*)&x2.w);
    int o = node * 16 + lane * 2;
    float4 z0 = emb0_4[o];
    float4 z1 = emb0_4[o + 1];
    float4 r0, r1;
    r0.x = (z0.x + sd * (p0.x + q0.x) + di * a0.x) * 0.25f;
    r0.y = (z0.y + sd * (p0.y + q0.y) + di * a0.y) * 0.25f;
    r0.z = (z0.z + sd * (p1.x + q1.x) + di * a0.z) * 0.25f;
    r0.w = (z0.w + sd * (p1.y + q1.y) + di * a0.w) * 0.25f;
    r1.x = (z1.x + sd * (p2.x + q2.x) + di * a1.x) * 0.25f;
    r1.y = (z1.y + sd * (p2.y + q2.y) + di * a1.y) * 0.25f;
    r1.z = (z1.z + sd * (p3.x + q3.x) + di * a1.z) * 0.25f;
    r1.w = (z1.w + sd * (p3.y + q3.y) + di * a1.w) * 0.25f;
    acc4[o]     = r0;
    acc4[o + 1] = r1;
}

__global__ void __launch_bounds__(256) k_prop_final(const __half* __restrict__ p2src,
                                                    const __half* __restrict__ p1src,
                                                    const float4* __restrict__ emb0_4,
                                                    float4* __restrict__ acc4) {
    int pair = (blockIdx.x * blockDim.x + threadIdx.x) >> 3;
    int lane = threadIdx.x & 7;
    if (pair >= NPAIR) return;
    int n0 = g_perm[2 * pair];
    int n1 = g_perm[2 * pair + 1];
    float4 A0 = make_float4(0.f, 0.f, 0.f, 0.f), A1 = A0, B0 = A0, B1 = A0;
    gather2((const uint4*)p2src, n0, n1, lane, A0, A1, B0, B1);
    store_final(p2src, p1src, emb0_4, acc4, n0, lane, A0, A1);
    store_final(p2src, p1src, emb0_4, acc4, n1, lane, B0, B1);
}

// ---------------- launch ----------------
extern "C" void kernel_launch(void* const* d_in, const int* in_sizes, int n_in,
                              void* d_out, int out_size) {
    const int*   ei   = (const int*)d_in[0];
    const int*   frm  = ei;
    const int*   to   = ei + NE;
    const float* emb  = (const float*)d_in[1];
    const float* uf   = (const float*)d_in[2];
    const float* bnf  = (const float*)d_in[3];
    const float* bgf  = (const float*)d_in[4];
    const float* Wu   = (const float*)d_in[5];
    const float* bu   = (const float*)d_in[6];
    const float* Wn   = (const float*)d_in[7];
    const float* bn   = (const float*)d_in[8];
    const float* Wg   = (const float*)d_in[9];
    const float* bg   = (const float*)d_in[10];

    float* out  = (float*)d_out;
    float* out0 = out;
    float* acc  = out + NN * D;

    __half* hA;
    __half* hB;
    void *pDeg, *pBins, *pBinCtr;
    cudaGetSymbolAddress((void**)&hA, g_h16A);
    cudaGetSymbolAddress((void**)&hB, g_h16B);
    cudaGetSymbolAddress(&pDeg, g_deg);
    cudaGetSymbolAddress(&pBins, g_bins);
    cudaGetSymbolAddress(&pBinCtr, g_bin_ctr);

    static cudaStream_t side = nullptr;
    static cudaEvent_t evFork = nullptr, evScan1 = nullptr, evJoin = nullptr;
    if (!side) {
        cudaStreamCreateWithFlags(&side, cudaStreamNonBlocking);
        cudaEventCreateWithFlags(&evFork, cudaEventDisableTiming);
        cudaEventCreateWithFlags(&evScan1, cudaEventDisableTiming);
        cudaEventCreateWithFlags(&evJoin, cudaEventDisableTiming);
    }

    // fork: emb0 on side stream
    cudaEventRecord(evFork, 0);
    cudaStreamWaitEvent(side, evFork, 0);
    k_emb0<<<(NN + 3) / 4, 256, 0, side>>>(emb, uf, bnf, bgf,
                                           Wu, bu, Wn, bn, Wg, bg, out0);

    // main: zero scratch, degree, scan1
    cudaMemsetAsync(pDeg, 0, NN * sizeof(int), 0);
    cudaMemsetAsync(pBins, 0, NBINS * sizeof(int), 0);
    cudaMemsetAsync(pBinCtr, 0, NBINS * sizeof(int), 0);
    k_degree<<<(NE + 255) / 256, 256>>>(to);
    k_scan1<<<NBLK, SCAN_BLK>>>();
    cudaEventRecord(evScan1, 0);

    // side: prescale p0 once dinv ready; overlaps scan3/scatter
    cudaStreamWaitEvent(side, evScan1, 0);
    k_prescale0<<<(NN + 3) / 4, 256, 0, side>>>(out0);
    cudaEventRecord(evJoin, side);

    // main: offsets + placement, then CSR scatter
    k_scan3_place<<<NBLK, SCAN_BLK>>>();
    k_scatter<<<(NE + 255) / 256, 256>>>(frm, to);

    cudaStreamWaitEvent(0, evJoin, 0);

    int prop_threads = NPAIR * 8;
    int prop_blocks  = (prop_threads + 255) / 256;
    k_prop_mid<<<prop_blocks, 256>>>(hA, hB);                 // p1: A -> B
    k_prop_mid<<<prop_blocks, 256>>>(hB, hA);                 // p2: B -> A
    k_prop_final<<<prop_blocks, 256>>>(hA, hB,
                                       (const float4*)out0, (float4*)acc);
}

// round 11
// speedup vs baseline: 1.1651x; 1.1651x over previous
#include <cuda_runtime.h>
#include <cuda_fp16.h>
#include <stdint.h>

#define NU 100000
#define NB 50000
#define NN 150000
#define D  64
#define NE 2400000

#define SCAN_BLK 1024
#define NBLK ((NN + SCAN_BLK - 1) / SCAN_BLK)   // 147
#define NBINS 256

// ---------------- scratch (device globals: allocation-free) ----------------
__device__ __half g_h16A[NN * D];    // fp16 prescaled: p0, then p2
__device__ __half g_h16B[NN * D];    // fp16 prescaled: p1
__device__ int    g_deg[NN];
__device__ float  g_dinv[NN];        // deg^-1/2
__device__ float  g_dinv2[NN];       // deg^-1
__device__ float  g_sdeg[NN];        // deg^1/2 (0 if deg=0)
__device__ int    g_off[NN + 1];
__device__ int    g_cur[NN];
__device__ int    g_csr[NE];         // frm only (weights separable -> prescaled)
__device__ int    g_partial[NBLK];
__device__ int    g_bins[NBINS];
__device__ int    g_bin_ctr[NBINS];
__device__ int    g_perm[NN];        // nodes sorted by degree (descending)

// ---------------- kernels ----------------

__global__ void k_emb0(const float* __restrict__ emb,
                       const float* __restrict__ uf,
                       const float* __restrict__ bnf,
                       const float* __restrict__ bgf,
                       const float* __restrict__ Wu, const float* __restrict__ bu,
                       const float* __restrict__ Wn, const float* __restrict__ bn,
                       const float* __restrict__ Wg, const float* __restrict__ bg,
                       float* __restrict__ out_emb0) {
    int node = blockIdx.x * 4 + (threadIdx.x >> 6);
    int d    = threadIdx.x & 63;
    if (node >= NN) return;
    float v = emb[node * D + d];
    if (node < NU) {
        const float* f = uf + node * 16;
        float s = bu[d];
#pragma unroll
        for (int k = 0; k < 16; k++) s += f[k] * Wu[k * D + d];
        v += s;
    } else {
        int b = node - NU;
        float s = bn[d] + bg[d];
        const float* fn = bnf + b * 8;
#pragma unroll
        for (int k = 0; k < 8; k++) s += fn[k] * Wn[k * D + d];
        const float* fg = bgf + b * 32;
#pragma unroll
        for (int k = 0; k < 32; k++) s += fg[k] * Wg[k * D + d];
        v += s;
    }
    out_emb0[node * D + d] = v;
}

// p0 = dinv * emb0 (fp16) — side stream, after scan1 (dinv) + emb0
__global__ void k_prescale0(const float* __restrict__ out_emb0) {
    int node = blockIdx.x * 4 + (threadIdx.x >> 6);
    int d    = threadIdx.x & 63;
    if (node >= NN) return;
    float di = g_dinv[node];
    int o = node * D + d;
    g_h16A[o] = __float2half_rn(di * out_emb0[o]);
}

// degree histogram: 4 edges per thread via int4
__global__ void k_degree(const int4* __restrict__ to4) {
    int i = blockIdx.x * blockDim.x + threadIdx.x;
    if (i < NE / 4) {
        int4 t = to4[i];
        atomicAdd(&g_deg[t.x], 1);
        atomicAdd(&g_deg[t.y], 1);
        atomicAdd(&g_deg[t.z], 1);
        atomicAdd(&g_deg[t.w], 1);
    }
}

__global__ void k_scan1() {
    __shared__ int s[SCAN_BLK / 32];
    __shared__ int hist[NBINS];
    int t = threadIdx.x;
    for (int b = t; b < NBINS; b += SCAN_BLK) hist[b] = 0;
    __syncthreads();
    int i = blockIdx.x * SCAN_BLK + t;
    int v = (i < NN) ? g_deg[i] : 0;
    if (i < NN) {
        float fv = (float)v;
        float di = (v > 0) ? rsqrtf(fv) : 0.0f;
        g_dinv[i]  = di;
        g_dinv2[i] = di * di;
        g_sdeg[i]  = (v > 0) ? sqrtf(fv) : 0.0f;
        atomicAdd(&hist[min(v, NBINS - 1)], 1);
    }
    int w = v;
#pragma unroll
    for (int o = 16; o > 0; o >>= 1) w += __shfl_down_sync(0xffffffffu, w, o);
    if ((t & 31) == 0) s[t >> 5] = w;
    __syncthreads();
    if (t < SCAN_BLK / 32) {
        int x = s[t];
#pragma unroll
        for (int o = 16; o > 0; o >>= 1) x += __shfl_down_sync(0xffffffffu, x, o);
        if (t == 0) g_partial[blockIdx.x] = x;
    }
    __syncthreads();
    for (int b = t; b < NBINS; b += SCAN_BLK)
        if (hist[b]) atomicAdd(&g_bins[b], hist[b]);
}

// fused: every block scans partials (block base) + bins (placement base),
// then per-block degree scan -> g_off/g_cur + descending-degree placement
__global__ void k_scan3_place() {
    __shared__ int s[SCAN_BLK];
    __shared__ int sp[256];
    __shared__ int sb[256];
    int t = threadIdx.x;

    if (t < 256) {
        sp[t] = (t < NBLK) ? g_partial[t] : 0;
        sb[t] = g_bins[t];
    }
    __syncthreads();
#pragma unroll
    for (int o = 1; o < 256; o <<= 1) {
        int yp = 0, yb = 0;
        if (t < 256 && t >= o) { yp = sp[t - o]; yb = sb[t - o]; }
        __syncthreads();
        if (t < 256) { sp[t] += yp; sb[t] += yb; }
        __syncthreads();
    }
    int blockBase = (blockIdx.x > 0) ? sp[blockIdx.x - 1] : 0;

    int i = blockIdx.x * SCAN_BLK + t;
    int v = (i < NN) ? g_deg[i] : 0;
    s[t] = v;
    __syncthreads();
#pragma unroll
    for (int o = 1; o < SCAN_BLK; o <<= 1) {
        int y = (t >= o) ? s[t - o] : 0;
        __syncthreads();
        s[t] += y;
        __syncthreads();
    }
    if (i < NN) {
        int ex = blockBase + s[t] - v;
        g_off[i] = ex;
        g_cur[i] = ex;
        int b = min(v, NBINS - 1);
        int binBase = (b > 0) ? sb[b - 1] : 0;
        int p = binBase + atomicAdd(&g_bin_ctr[b], 1);
        g_perm[NN - 1 - p] = i;
    }
    if (i == NN - 1) g_off[NN] = NE;
}

// scatter: 4 edges per thread via int4 loads of frm and to
__global__ void k_scatter(const int4* __restrict__ frm4, const int4* __restrict__ to4) {
    int i = blockIdx.x * blockDim.x + threadIdx.x;
    if (i < NE / 4) {
        int4 f = frm4[i];
        int4 t = to4[i];
        int p;
        p = atomicAdd(&g_cur[t.x], 1); g_csr[p] = f.x;
        p = atomicAdd(&g_cur[t.y], 1); g_csr[p] = f.y;
        p = atomicAdd(&g_cur[t.z], 1); g_csr[p] = f.z;
        p = atomicAdd(&g_cur[t.w], 1); g_csr[p] = f.w;
    }
}

// gather core: 8 lanes/node; pure unweighted sum of prescaled fp16 rows
// (R9 configuration — protected; R10's 2-node interleave regressed)
__device__ __forceinline__ void gather_node(const uint4* __restrict__ src16,
                                            int node, int lane,
                                            float4& a0, float4& a1) {
    int s = g_off[node];
    int e = g_off[node + 1];
#pragma unroll 4
    for (int idx = s; idx < e; idx++) {
        int   f = __ldg(&g_csr[idx]);
        uint4 x = src16[f * 8 + lane];
        float2 f0 = __half22float2(*(const __half2*)&x.x);
        float2 f1 = __half22float2(*(const __half2*)&x.y);
        float2 f2 = __half22float2(*(const __half2*)&x.z);
        float2 f3 = __half22float2(*(const __half2*)&x.w);
        a0.x += f0.x;  a0.y += f0.y;
        a0.z += f1.x;  a0.w += f1.y;
        a1.x += f2.x;  a1.y += f2.y;
        a1.z += f3.x;  a1.w += f3.y;
    }
}

// mid layer: S = gather(p_k); store p_{k+1} = dinv^2 * S  (fp16)
__global__ void __launch_bounds__(256) k_prop_mid(const __half* __restrict__ src,
                                                  __half* __restrict__ dst) {
    int slot = (blockIdx.x * blockDim.x + threadIdx.x) >> 3;
    int lane = threadIdx.x & 7;
    if (slot >= NN) return;
    int node = g_perm[slot];
    float4 a0 = make_float4(0.f, 0.f, 0.f, 0.f);
    float4 a1 = make_float4(0.f, 0.f, 0.f, 0.f);
    gather_node((const uint4*)src, node, lane, a0, a1);
    float d2 = g_dinv2[node];
    __half2 h0 = __floats2half2_rn(d2 * a0.x, d2 * a0.y);
    __half2 h1 = __floats2half2_rn(d2 * a0.z, d2 * a0.w);
    __half2 h2 = __floats2half2_rn(d2 * a1.x, d2 * a1.y);
    __half2 h3 = __floats2half2_rn(d2 * a1.z, d2 * a1.w);
    uint4 hx;
    hx.x = *(const unsigned*)&h0;
    hx.y = *(const unsigned*)&h1;
    hx.z = *(const unsigned*)&h2;
    hx.w = *(const unsigned*)&h3;
    ((uint4*)dst)[node * 8 + lane] = hx;
}

// final: S3 = gather(p2); acc = (emb0 + sdeg*(p1 + p2) + dinv*S3) / 4
__global__ void __launch_bounds__(256) k_prop_final(const __half* __restrict__ p2src,
                                                    const __half* __restrict__ p1src,
                                                    const float4* __restrict__ emb0_4,
                                                    float4* __restrict__ acc4) {
    int slot = (blockIdx.x * blockDim.x + threadIdx.x) >> 3;
    int lane = threadIdx.x & 7;
    if (slot >= NN) return;
    int node = g_perm[slot];
    float4 a0 = make_float4(0.f, 0.f, 0.f, 0.f);
    float4 a1 = make_float4(0.f, 0.f, 0.f, 0.f);
    gather_node((const uint4*)p2src, node, lane, a0, a1);   // S3

    float di = g_dinv[node];
    float sd = g_sdeg[node];

    int ho = node * 8 + lane;
    uint4 x1 = ((const uint4*)p1src)[ho];
    uint4 x2 = ((const uint4*)p2src)[ho];
    float2 p0 = __half22float2(*(const __half2*)&x1.x);
    float2 p1 = __half22float2(*(const __half2*)&x1.y);
    float2 p2 = __half22float2(*(const __half2*)&x1.z);
    float2 p3 = __half22float2(*(const __half2*)&x1.w);
    float2 q0 = __half22float2(*(const __half2*)&x2.x);
    float2 q1 = __half22float2(*(const __half2*)&x2.y);
    float2 q2 = __half22float2(*(const __half2*)&x2.z);
    float2 q3 = __half22float2(*(const __half2*)&x2.w);

    int o = node * 16 + lane * 2;
    float4 z0 = emb0_4[o];
    float4 z1 = emb0_4[o + 1];

    float4 r0, r1;
    r0.x = (z0.x + sd * (p0.x + q0.x) + di * a0.x) * 0.25f;
    r0.y = (z0.y + sd * (p0.y + q0.y) + di * a0.y) * 0.25f;
    r0.z = (z0.z + sd * (p1.x + q1.x) + di * a0.z) * 0.25f;
    r0.w = (z0.w + sd * (p1.y + q1.y) + di * a0.w) * 0.25f;
    r1.x = (z1.x + sd * (p2.x + q2.x) + di * a1.x) * 0.25f;
    r1.y = (z1.y + sd * (p2.y + q2.y) + di * a1.y) * 0.25f;
    r1.z = (z1.z + sd * (p3.x + q3.x) + di * a1.z) * 0.25f;
    r1.w = (z1.w + sd * (p3.y + q3.y) + di * a1.w) * 0.25f;
    acc4[o]     = r0;
    acc4[o + 1] = r1;
}

// ---------------- launch ----------------
extern "C" void kernel_launch(void* const* d_in, const int* in_sizes, int n_in,
                              void* d_out, int out_size) {
    const int*   ei   = (const int*)d_in[0];
    const int*   frm  = ei;
    const int*   to   = ei + NE;
    const float* emb  = (const float*)d_in[1];
    const float* uf   = (const float*)d_in[2];
    const float* bnf  = (const float*)d_in[3];
    const float* bgf  = (const float*)d_in[4];
    const float* Wu   = (const float*)d_in[5];
    const float* bu   = (const float*)d_in[6];
    const float* Wn   = (const float*)d_in[7];
    const float* bn   = (const float*)d_in[8];
    const float* Wg   = (const float*)d_in[9];
    const float* bg   = (const float*)d_in[10];

    float* out  = (float*)d_out;
    float* out0 = out;              // emb0 (fp32, exact)
    float* acc  = out + NN * D;     // final output, written once

    __half* hA;
    __half* hB;
    void *pDeg, *pBins, *pBinCtr;
    cudaGetSymbolAddress((void**)&hA, g_h16A);
    cudaGetSymbolAddress((void**)&hB, g_h16B);
    cudaGetSymbolAddress(&pDeg, g_deg);
    cudaGetSymbolAddress(&pBins, g_bins);
    cudaGetSymbolAddress(&pBinCtr, g_bin_ctr);

    static cudaStream_t side = nullptr;
    static cudaEvent_t evFork = nullptr, evScan1 = nullptr, evJoin = nullptr;
    if (!side) {
        cudaStreamCreateWithFlags(&side, cudaStreamNonBlocking);
        cudaEventCreateWithFlags(&evFork, cudaEventDisableTiming);
        cudaEventCreateWithFlags(&evScan1, cudaEventDisableTiming);
        cudaEventCreateWithFlags(&evJoin, cudaEventDisableTiming);
    }

    // fork: emb0 on side stream (no dependency on edge chain)
    cudaEventRecord(evFork, 0);
    cudaStreamWaitEvent(side, evFork, 0);
    k_emb0<<<(NN + 3) / 4, 256, 0, side>>>(emb, uf, bnf, bgf,
                                           Wu, bu, Wn, bn, Wg, bg, out0);

    // main: zero scratch, degree, scan1
    cudaMemsetAsync(pDeg, 0, NN * sizeof(int), 0);
    cudaMemsetAsync(pBins, 0, NBINS * sizeof(int), 0);
    cudaMemsetAsync(pBinCtr, 0, NBINS * sizeof(int), 0);
    k_degree<<<(NE / 4 + 255) / 256, 256>>>((const int4*)to);
    k_scan1<<<NBLK, SCAN_BLK>>>();
    cudaEventRecord(evScan1, 0);

    // side: prescale p0 once dinv ready; overlaps scan3/scatter
    cudaStreamWaitEvent(side, evScan1, 0);
    k_prescale0<<<(NN + 3) / 4, 256, 0, side>>>(out0);
    cudaEventRecord(evJoin, side);

    // main: offsets + placement, then CSR scatter
    k_scan3_place<<<NBLK, SCAN_BLK>>>();
    k_scatter<<<(NE / 4 + 255) / 256, 256>>>((const int4*)frm, (const int4*)to);

    // join: props need CSR (main) + p0 (side)
    cudaStreamWaitEvent(0, evJoin, 0);

    int prop_threads = NN * 8;
    int prop_blocks  = (prop_threads + 255) / 256;
    k_prop_mid<<<prop_blocks, 256>>>(hA, hB);                 // p1: A -> B
    k_prop_mid<<<prop_blocks, 256>>>(hB, hA);                 // p2: B -> A
    k_prop_final<<<prop_blocks, 256>>>(hA, hB,
                                       (const float4*)out0, (float4*)acc);
}

// round 12
// speedup vs baseline: 1.2390x; 1.0635x over previous
#include <cuda_runtime.h>
#include <cuda_fp16.h>
#include <stdint.h>

#define NU 100000
#define NB 50000
#define NN 150000
#define D  64
#define NE 2400000

#define SCAN_BLK 1024
#define NBLK ((NN + SCAN_BLK - 1) / SCAN_BLK)   // 147
#define NBINS 256

// ---------------- scratch (device globals: allocation-free) ----------------
__device__ __half g_h16A[NN * D];    // fp16 prescaled: p0, then p2
__device__ __half g_h16B[NN * D];    // fp16 prescaled: p1
__device__ int    g_deg[NN];
__device__ float  g_dinv[NN];        // deg^-1/2
__device__ float  g_dinv2[NN];       // deg^-1
__device__ float  g_sdeg[NN];        // deg^1/2 (0 if deg=0)
__device__ int    g_off[NN + 1];
__device__ int    g_cur[NN];
__device__ int    g_csr[NE];         // frm only (weights separable -> prescaled)
__device__ int    g_partial[NBLK];
__device__ int    g_bins[NBINS];
__device__ int    g_bin_ctr[NBINS];
__device__ int    g_perm[NN];        // nodes sorted by degree (descending)

// ---------------- kernels ----------------

// emb0 FUSED with prescale: v -> out0 (fp32) and p0 = dinv*v (fp16).
// Runs after scan1 (needs g_dinv).
__global__ void k_emb0_fused(const float* __restrict__ emb,
                             const float* __restrict__ uf,
                             const float* __restrict__ bnf,
                             const float* __restrict__ bgf,
                             const float* __restrict__ Wu, const float* __restrict__ bu,
                             const float* __restrict__ Wn, const float* __restrict__ bn,
                             const float* __restrict__ Wg, const float* __restrict__ bg,
                             float* __restrict__ out_emb0) {
    int node = blockIdx.x * 4 + (threadIdx.x >> 6);
    int d    = threadIdx.x & 63;
    if (node >= NN) return;
    float v = emb[node * D + d];
    if (node < NU) {
        const float* f = uf + node * 16;
        float s = bu[d];
#pragma unroll
        for (int k = 0; k < 16; k++) s += f[k] * Wu[k * D + d];
        v += s;
    } else {
        int b = node - NU;
        float s = bn[d] + bg[d];
        const float* fn = bnf + b * 8;
#pragma unroll
        for (int k = 0; k < 8; k++) s += fn[k] * Wn[k * D + d];
        const float* fg = bgf + b * 32;
#pragma unroll
        for (int k = 0; k < 32; k++) s += fg[k] * Wg[k * D + d];
        v += s;
    }
    int o = node * D + d;
    out_emb0[o] = v;
    g_h16A[o]   = __float2half_rn(g_dinv[node] * v);
}

// degree histogram: 4 edges per thread via int4
__global__ void k_degree(const int4* __restrict__ to4) {
    int i = blockIdx.x * blockDim.x + threadIdx.x;
    if (i < NE / 4) {
        int4 t = to4[i];
        atomicAdd(&g_deg[t.x], 1);
        atomicAdd(&g_deg[t.y], 1);
        atomicAdd(&g_deg[t.z], 1);
        atomicAdd(&g_deg[t.w], 1);
    }
}

__global__ void k_scan1() {
    __shared__ int s[SCAN_BLK / 32];
    __shared__ int hist[NBINS];
    int t = threadIdx.x;
    for (int b = t; b < NBINS; b += SCAN_BLK) hist[b] = 0;
    __syncthreads();
    int i = blockIdx.x * SCAN_BLK + t;
    int v = (i < NN) ? g_deg[i] : 0;
    if (i < NN) {
        float fv = (float)v;
        float di = (v > 0) ? rsqrtf(fv) : 0.0f;
        g_dinv[i]  = di;
        g_dinv2[i] = di * di;
        g_sdeg[i]  = (v > 0) ? sqrtf(fv) : 0.0f;
        atomicAdd(&hist[min(v, NBINS - 1)], 1);
    }
    int w = v;
#pragma unroll
    for (int o = 16; o > 0; o >>= 1) w += __shfl_down_sync(0xffffffffu, w, o);
    if ((t & 31) == 0) s[t >> 5] = w;
    __syncthreads();
    if (t < SCAN_BLK / 32) {
        int x = s[t];
#pragma unroll
        for (int o = 16; o > 0; o >>= 1) x += __shfl_down_sync(0xffffffffu, x, o);
        if (t == 0) g_partial[blockIdx.x] = x;
    }
    __syncthreads();
    for (int b = t; b < NBINS; b += SCAN_BLK)
        if (hist[b]) atomicAdd(&g_bins[b], hist[b]);
}

// fused: every block scans partials (block base) + bins (placement base),
// then per-block degree scan -> g_off/g_cur + descending-degree placement
__global__ void k_scan3_place() {
    __shared__ int s[SCAN_BLK];
    __shared__ int sp[256];
    __shared__ int sb[256];
    int t = threadIdx.x;

    if (t < 256) {
        sp[t] = (t < NBLK) ? g_partial[t] : 0;
        sb[t] = g_bins[t];
    }
    __syncthreads();
#pragma unroll
    for (int o = 1; o < 256; o <<= 1) {
        int yp = 0, yb = 0;
        if (t < 256 && t >= o) { yp = sp[t - o]; yb = sb[t - o]; }
        __syncthreads();
        if (t < 256) { sp[t] += yp; sb[t] += yb; }
        __syncthreads();
    }
    int blockBase = (blockIdx.x > 0) ? sp[blockIdx.x - 1] : 0;

    int i = blockIdx.x * SCAN_BLK + t;
    int v = (i < NN) ? g_deg[i] : 0;
    s[t] = v;
    __syncthreads();
#pragma unroll
    for (int o = 1; o < SCAN_BLK; o <<= 1) {
        int y = (t >= o) ? s[t - o] : 0;
        __syncthreads();
        s[t] += y;
        __syncthreads();
    }
    if (i < NN) {
        int ex = blockBase + s[t] - v;
        g_off[i] = ex;
        g_cur[i] = ex;
        int b = min(v, NBINS - 1);
        int binBase = (b > 0) ? sb[b - 1] : 0;
        int p = binBase + atomicAdd(&g_bin_ctr[b], 1);
        g_perm[NN - 1 - p] = i;
    }
    if (i == NN - 1) g_off[NN] = NE;
}

// scatter: 4 edges per thread via int4 loads of frm and to
__global__ void k_scatter(const int4* __restrict__ frm4, const int4* __restrict__ to4) {
    int i = blockIdx.x * blockDim.x + threadIdx.x;
    if (i < NE / 4) {
        int4 f = frm4[i];
        int4 t = to4[i];
        int p;
        p = atomicAdd(&g_cur[t.x], 1); g_csr[p] = f.x;
        p = atomicAdd(&g_cur[t.y], 1); g_csr[p] = f.y;
        p = atomicAdd(&g_cur[t.z], 1); g_csr[p] = f.z;
        p = atomicAdd(&g_cur[t.w], 1); g_csr[p] = f.w;
    }
}

// gather core: 8 lanes/node; pure unweighted sum of prescaled fp16 rows
// (R9 configuration — protected)
__device__ __forceinline__ void gather_node(const uint4* __restrict__ src16,
                                            int node, int lane,
                                            float4& a0, float4& a1) {
    int s = g_off[node];
    int e = g_off[node + 1];
#pragma unroll 4
    for (int idx = s; idx < e; idx++) {
        int   f = __ldg(&g_csr[idx]);
        uint4 x = src16[f * 8 + lane];
        float2 f0 = __half22float2(*(const __half2*)&x.x);
        float2 f1 = __half22float2(*(const __half2*)&x.y);
        float2 f2 = __half22float2(*(const __half2*)&x.z);
        float2 f3 = __half22float2(*(const __half2*)&x.w);
        a0.x += f0.x;  a0.y += f0.y;
        a0.z += f1.x;  a0.w += f1.y;
        a1.x += f2.x;  a1.y += f2.y;
        a1.z += f3.x;  a1.w += f3.y;
    }
}

// mid layer: S = gather(p_k); store p_{k+1} = dinv^2 * S  (fp16)
__global__ void __launch_bounds__(256) k_prop_mid(const __half* __restrict__ src,
                                                  __half* __restrict__ dst) {
    int slot = (blockIdx.x * blockDim.x + threadIdx.x) >> 3;
    int lane = threadIdx.x & 7;
    if (slot >= NN) return;
    int node = g_perm[slot];
    float4 a0 = make_float4(0.f, 0.f, 0.f, 0.f);
    float4 a1 = make_float4(0.f, 0.f, 0.f, 0.f);
    gather_node((const uint4*)src, node, lane, a0, a1);
    float d2 = g_dinv2[node];
    __half2 h0 = __floats2half2_rn(d2 * a0.x, d2 * a0.y);
    __half2 h1 = __floats2half2_rn(d2 * a0.z, d2 * a0.w);
    __half2 h2 = __floats2half2_rn(d2 * a1.x, d2 * a1.y);
    __half2 h3 = __floats2half2_rn(d2 * a1.z, d2 * a1.w);
    uint4 hx;
    hx.x = *(const unsigned*)&h0;
    hx.y = *(const unsigned*)&h1;
    hx.z = *(const unsigned*)&h2;
    hx.w = *(const unsigned*)&h3;
    ((uint4*)dst)[node * 8 + lane] = hx;
}

// final: S3 = gather(p2); acc = (emb0 + sdeg*(p1 + p2) + dinv*S3) / 4
__global__ void __launch_bounds__(256) k_prop_final(const __half* __restrict__ p2src,
                                                    const __half* __restrict__ p1src,
                                                    const float4* __restrict__ emb0_4,
                                                    float4* __restrict__ acc4) {
    int slot = (blockIdx.x * blockDim.x + threadIdx.x) >> 3;
    int lane = threadIdx.x & 7;
    if (slot >= NN) return;
    int node = g_perm[slot];
    float4 a0 = make_float4(0.f, 0.f, 0.f, 0.f);
    float4 a1 = make_float4(0.f, 0.f, 0.f, 0.f);
    gather_node((const uint4*)p2src, node, lane, a0, a1);   // S3

    float di = g_dinv[node];
    float sd = g_sdeg[node];

    int ho = node * 8 + lane;
    uint4 x1 = ((const uint4*)p1src)[ho];
    uint4 x2 = ((const uint4*)p2src)[ho];
    float2 p0 = __half22float2(*(const __half2*)&x1.x);
    float2 p1 = __half22float2(*(const __half2*)&x1.y);
    float2 p2 = __half22float2(*(const __half2*)&x1.z);
    float2 p3 = __half22float2(*(const __half2*)&x1.w);
    float2 q0 = __half22float2(*(const __half2*)&x2.x);
    float2 q1 = __half22float2(*(const __half2*)&x2.y);
    float2 q2 = __half22float2(*(const __half2*)&x2.z);
    float2 q3 = __half22float2(*(const __half2*)&x2.w);

    int o = node * 16 + lane * 2;
    float4 z0 = emb0_4[o];
    float4 z1 = emb0_4[o + 1];

    float4 r0, r1;
    r0.x = (z0.x + sd * (p0.x + q0.x) + di * a0.x) * 0.25f;
    r0.y = (z0.y + sd * (p0.y + q0.y) + di * a0.y) * 0.25f;
    r0.z = (z0.z + sd * (p1.x + q1.x) + di * a0.z) * 0.25f;
    r0.w = (z0.w + sd * (p1.y + q1.y) + di * a0.w) * 0.25f;
    r1.x = (z1.x + sd * (p2.x + q2.x) + di * a1.x) * 0.25f;
    r1.y = (z1.y + sd * (p2.y + q2.y) + di * a1.y) * 0.25f;
    r1.z = (z1.z + sd * (p3.x + q3.x) + di * a1.z) * 0.25f;
    r1.w = (z1.w + sd * (p3.y + q3.y) + di * a1.w) * 0.25f;
    acc4[o]     = r0;
    acc4[o + 1] = r1;
}

// ---------------- launch ----------------
extern "C" void kernel_launch(void* const* d_in, const int* in_sizes, int n_in,
                              void* d_out, int out_size) {
    const int*   ei   = (const int*)d_in[0];
    const int*   frm  = ei;
    const int*   to   = ei + NE;
    const float* emb  = (const float*)d_in[1];
    const float* uf   = (const float*)d_in[2];
    const float* bnf  = (const float*)d_in[3];
    const float* bgf  = (const float*)d_in[4];
    const float* Wu   = (const float*)d_in[5];
    const float* bu   = (const float*)d_in[6];
    const float* Wn   = (const float*)d_in[7];
    const float* bn   = (const float*)d_in[8];
    const float* Wg   = (const float*)d_in[9];
    const float* bg   = (const float*)d_in[10];

    float* out  = (float*)d_out;
    float* out0 = out;              // emb0 (fp32, exact)
    float* acc  = out + NN * D;     // final output, written once

    __half* hA;
    __half* hB;
    void *pDeg, *pBins, *pBinCtr;
    cudaGetSymbolAddress((void**)&hA, g_h16A);
    cudaGetSymbolAddress((void**)&hB, g_h16B);
    cudaGetSymbolAddress(&pDeg, g_deg);
    cudaGetSymbolAddress(&pBins, g_bins);
    cudaGetSymbolAddress(&pBinCtr, g_bin_ctr);

    static cudaStream_t side = nullptr;
    static cudaEvent_t evScan1 = nullptr, evJoin = nullptr;
    if (!side) {
        cudaStreamCreateWithFlags(&side, cudaStreamNonBlocking);
        cudaEventCreateWithFlags(&evScan1, cudaEventDisableTiming);
        cudaEventCreateWithFlags(&evJoin, cudaEventDisableTiming);
    }

    // main: zero scratch, degree, scan1  (critical prefix, ~19us)
    cudaMemsetAsync(pDeg, 0, NN * sizeof(int), 0);
    cudaMemsetAsync(pBins, 0, NBINS * sizeof(int), 0);
    cudaMemsetAsync(pBinCtr, 0, NBINS * sizeof(int), 0);
    k_degree<<<(NE / 4 + 255) / 256, 256>>>((const int4*)to);
    k_scan1<<<NBLK, SCAN_BLK>>>();
    cudaEventRecord(evScan1, 0);

    // side: CSR offsets + placement + scatter, overlapping emb0_fused on main
    cudaStreamWaitEvent(side, evScan1, 0);
    k_scan3_place<<<NBLK, SCAN_BLK, 0, side>>>();
    k_scatter<<<(NE / 4 + 255) / 256, 256, 0, side>>>((const int4*)frm, (const int4*)to);
    cudaEventRecord(evJoin, side);

    // main: fused emb0 + prescale (needs dinv from scan1)
    k_emb0_fused<<<(NN + 3) / 4, 256>>>(emb, uf, bnf, bgf,
                                        Wu, bu, Wn, bn, Wg, bg, out0);

    // join: props need p0 (main) + CSR (side)
    cudaStreamWaitEvent(0, evJoin, 0);

    int prop_threads = NN * 8;
    int prop_blocks  = (prop_threads + 255) / 256;
    k_prop_mid<<<prop_blocks, 256>>>(hA, hB);                 // p1: A -> B
    k_prop_mid<<<prop_blocks, 256>>>(hB, hA);                 // p2: B -> A
    k_prop_final<<<prop_blocks, 256>>>(hA, hB,
                                       (const float4*)out0, (float4*)acc);
}